// round 6
// baseline (speedup 1.0000x reference)
#include <cuda_runtime.h>

#define NW 6
#define NL 4
#define HP 112
#define WP 112
#define NB 8
#define OC 16
#define NPIX (NB*HP*WP)

__device__ float g_T[6*27];
__device__ float g_y[NB*OC*HP*WP];

// ---------------------------------------------------------------------------
// Kernel 0 (v5): 512 threads. Warps 0-7 simulate one basis state each with
// register-resident amplitudes + warp shuffles. Phase D (M = Phi^dag Z Phi)
// uses all 512 threads, one (q,i,jj) item each. Phase E exploits that the
// half-angle->full-angle coefficient is nonzero for only 2 (bi,bj) combos
// per wire per basis term: 8 contributing pairs instead of 64.
// ---------------------------------------------------------------------------
__global__ void k_precompute(const float* __restrict__ w)
{
    __shared__ float2 sU[24][4];
    __shared__ float2 phi[8][64];
    __shared__ float  Mre[6][8][8];
    __shared__ float  Mim[6][8][8];

    const int tid  = threadIdx.x;          // 512 threads = 16 warps
    const int wrp  = tid >> 5;
    const int lane = tid & 31;
    const unsigned FULL = 0xFFFFFFFFu;

    if (tid < 24) {
        const float ph = w[tid*3 + 0];
        const float th = w[tid*3 + 1];
        const float om = w[tid*3 + 2];
        const float ch = cosf(0.5f * th), sh = sinf(0.5f * th);
        float cp, sp, cm, sm;
        sincosf(-0.5f * (ph + om), &sp, &cp);
        sincosf(-0.5f * (ph - om), &sm, &cm);
        sU[tid][0] = make_float2( cp*ch,  sp*ch);
        sU[tid][1] = make_float2(-cm*sh,  sm*sh);
        sU[tid][2] = make_float2( cm*sh,  sm*sh);
        sU[tid][3] = make_float2( cp*ch, -sp*ch);
    }
    __syncthreads();

    if (wrp < 8) {
        float ar = (lane == wrp * 8) ? 1.f : 0.f, ai = 0.f;
        float br = (lane + 32 == wrp * 8) ? 1.f : 0.f, bi = 0.f;

        for (int l = 0; l < NL; l++) {
            #pragma unroll
            for (int q = 0; q < NW; q++) {
                const float2 u00 = sU[l*6+q][0], u01 = sU[l*6+q][1];
                const float2 u10 = sU[l*6+q][2], u11 = sU[l*6+q][3];
                if (q == 0) {
                    const float nar = u00.x*ar - u00.y*ai + u01.x*br - u01.y*bi;
                    const float nai = u00.x*ai + u00.y*ar + u01.x*bi + u01.y*br;
                    const float nbr = u10.x*ar - u10.y*ai + u11.x*br - u11.y*bi;
                    const float nbi = u10.x*ai + u10.y*ar + u11.x*bi + u11.y*br;
                    ar = nar; ai = nai; br = nbr; bi = nbi;
                } else {
                    const int stride = 1 << (5 - q);
                    const float par = __shfl_xor_sync(FULL, ar, stride);
                    const float pai = __shfl_xor_sync(FULL, ai, stride);
                    const float pbr = __shfl_xor_sync(FULL, br, stride);
                    const float pbi = __shfl_xor_sync(FULL, bi, stride);
                    const bool hi = (lane & stride) != 0;
                    {
                        const float v0r = hi ? par : ar, v0i = hi ? pai : ai;
                        const float v1r = hi ? ar : par, v1i = hi ? ai : pai;
                        const float2 cL = hi ? u10 : u00, cR = hi ? u11 : u01;
                        const float nr = cL.x*v0r - cL.y*v0i + cR.x*v1r - cR.y*v1i;
                        const float ni = cL.x*v0i + cL.y*v0r + cR.x*v1i + cR.y*v1r;
                        ar = nr; ai = ni;
                    }
                    {
                        const float v0r = hi ? pbr : br, v0i = hi ? pbi : bi;
                        const float v1r = hi ? br : pbr, v1i = hi ? bi : pbi;
                        const float2 cL = hi ? u10 : u00, cR = hi ? u11 : u01;
                        const float nr = cL.x*v0r - cL.y*v0i + cR.x*v1r - cR.y*v1i;
                        const float ni = cL.x*v0i + cL.y*v0r + cR.x*v1i + cR.y*v1r;
                        br = nr; bi = ni;
                    }
                }
            }
            const int r = l % (NW - 1) + 1;
            int i0 = lane, i1 = lane + 32;
            #pragma unroll
            for (int q = NW - 1; q >= 0; q--) {
                const int cpos = 5 - q;
                const int tpos = 5 - ((q + r) % NW);
                i0 ^= ((i0 >> cpos) & 1) << tpos;
                i1 ^= ((i1 >> cpos) & 1) << tpos;
            }
            const float g0ar = __shfl_sync(FULL, ar, i0 & 31);
            const float g0ai = __shfl_sync(FULL, ai, i0 & 31);
            const float g0br = __shfl_sync(FULL, br, i0 & 31);
            const float g0bi = __shfl_sync(FULL, bi, i0 & 31);
            const float g1ar = __shfl_sync(FULL, ar, i1 & 31);
            const float g1ai = __shfl_sync(FULL, ai, i1 & 31);
            const float g1br = __shfl_sync(FULL, br, i1 & 31);
            const float g1bi = __shfl_sync(FULL, bi, i1 & 31);
            ar = (i0 < 32) ? g0ar : g0br;
            ai = (i0 < 32) ? g0ai : g0bi;
            br = (i1 < 32) ? g1ar : g1br;
            bi = (i1 < 32) ? g1ai : g1bi;
        }
        phi[wrp][lane]      = make_float2(ar, ai);
        phi[wrp][lane + 32] = make_float2(br, bi);
    }
    __syncthreads();

    // Phase D: one (q,i,jj) item per thread (384 items, 512 threads)
    if (tid < 6 * 64) {
        const int q = tid / 64, ij = tid % 64, i = ij / 8, jj = ij % 8;
        float re = 0.f, im = 0.f;
        #pragma unroll 16
        for (int t = 0; t < 64; t++) {
            const float z = ((t >> (5 - q)) & 1) ? -1.f : 1.f;
            const float2 a = phi[i][t], b = phi[jj][t];
            re += z * (a.x * b.x + a.y * b.y);
            im += z * (a.x * b.y - a.y * b.x);
        }
        Mre[q][i][jj] = re;
        Mim[q][i][jj] = im;
    }
    __syncthreads();

    // Phase E: only 8 (i,jj) pairs contribute per basis term.
    // per-wire options: t=0 -> (0,0,+),(1,1,+) ; t=1 -> (0,0,+),(1,1,-) ;
    //                   t=2 -> (0,1,+),(1,0,+)  (each coefficient 0.5)
    if (tid < 6 * 27) {
        const int q = tid / 27, term = tid % 27;
        const int tt[3] = { term / 9, (term / 3) % 3, term % 3 };
        float acc = 0.f;
        #pragma unroll
        for (int k = 0; k < 8; k++) {
            int i = 0, jj = 0;
            float sgn = 0.125f;
            #pragma unroll
            for (int c = 0; c < 3; c++) {
                const int sel = (k >> c) & 1;
                const int t = tt[c];
                int bi, bj;
                if (t == 2) { bi = sel ^ 1; bj = sel; }       // (0,1),(1,0)
                else {
                    bi = sel; bj = sel;                        // (0,0),(1,1)
                    if (t == 1 && sel == 1) sgn = -sgn;
                }
                i  |= bi << (2 - c);
                jj |= bj << (2 - c);
            }
            const int kph = (__popc(i) - __popc(jj)) & 3;
            const float mre = Mre[q][i][jj], mim = Mim[q][i][jj];
            const float f = (kph == 0) ? mre : (kph == 1) ? -mim
                          : (kph == 2) ? -mre : mim;
            acc += sgn * f;
        }
        g_T[tid] = acc;
    }
}

// ---------------------------------------------------------------------------
// Kernel 1: two adjacent patch pixels per thread (float4 reads, float2
// writes per channel): 2x2 mean -> trig basis -> 6 exps -> FC -> LN -> ReLU.
// ---------------------------------------------------------------------------
__global__ void k_pixels(const float* __restrict__ x,
                         const float* __restrict__ fcw,
                         const float* __restrict__ fcb,
                         const float* __restrict__ lng,
                         const float* __restrict__ lnb)
{
    __shared__ float sT[162], sFC[96], sFB[16], sG[16], sB[16];
    const int tid = threadIdx.x;
    if (tid < 162) sT[tid] = g_T[tid];
    if (tid < 96)  sFC[tid] = fcw[tid];
    if (tid >= 96  && tid < 112) sFB[tid - 96]  = fcb[tid - 96];
    if (tid >= 112 && tid < 128) sG [tid - 112] = lng[tid - 112];
    if (tid >= 128 && tid < 144) sB [tid - 128] = lnb[tid - 128];
    __syncthreads();

    const int pp = blockIdx.x * blockDim.x + tid;
    if (pp >= NPIX / 2) return;
    const int WPH = WP / 2;
    const int b   = pp / (HP * WPH);
    const int rem = pp % (HP * WPH);
    const int hp  = rem / WPH, wpp = rem % WPH;

    float g0[3][3], g1[3][3];
    #pragma unroll
    for (int c = 0; c < 3; c++) {
        const float* base = x + (((long)(b * 3 + c) * 224 + 2 * hp) * 224 + 4 * wpp);
        const float4 r0 = *reinterpret_cast<const float4*>(base);
        const float4 r1 = *reinterpret_cast<const float4*>(base + 224);
        const float a0 = 0.25f * (r0.x + r0.y + r1.x + r1.y);
        const float a1 = 0.25f * (r0.z + r0.w + r1.z + r1.w);
        float sn, cs;
        sincosf(a0, &sn, &cs);
        g0[c][0] = 1.f; g0[c][1] = cs; g0[c][2] = sn;
        sincosf(a1, &sn, &cs);
        g1[c][0] = 1.f; g1[c][1] = cs; g1[c][2] = sn;
    }

    float2 vout[OC];
    #pragma unroll
    for (int half = 0; half < 2; half++) {
        float (*gg)[3] = half ? g1 : g0;

        float e[6];
        #pragma unroll
        for (int q = 0; q < 6; q++) e[q] = 0.f;
        #pragma unroll
        for (int t0 = 0; t0 < 3; t0++)
            #pragma unroll
            for (int t1 = 0; t1 < 3; t1++) {
                const float p01 = gg[0][t0] * gg[1][t1];
                #pragma unroll
                for (int t2 = 0; t2 < 3; t2++) {
                    const float bas = p01 * gg[2][t2];
                    const int t = (t0 * 3 + t1) * 3 + t2;
                    #pragma unroll
                    for (int q = 0; q < 6; q++) e[q] += sT[q * 27 + t] * bas;
                }
            }

        float y[OC], mu = 0.f;
        #pragma unroll
        for (int o = 0; o < OC; o++) {
            float acc = sFB[o];
            #pragma unroll
            for (int q = 0; q < 6; q++) acc += sFC[o * 6 + q] * e[q];
            y[o] = acc;
            mu += acc;
        }
        mu *= (1.f / OC);
        float var = 0.f;
        #pragma unroll
        for (int o = 0; o < OC; o++) { const float d = y[o] - mu; var += d * d; }
        var *= (1.f / OC);
        const float inv = rsqrtf(var + 1e-5f);
        #pragma unroll
        for (int o = 0; o < OC; o++) {
            const float v = fmaxf((y[o] - mu) * inv * sG[o] + sB[o], 0.f);
            if (half) vout[o].y = v; else vout[o].x = v;
        }
    }

    #pragma unroll
    for (int o = 0; o < OC; o++) {
        *reinterpret_cast<float2*>(
            &g_y[(((long)b * OC + o) * HP + hp) * WP + 2 * wpp]) = vout[o];
    }
}

// ---------------------------------------------------------------------------
// Kernel 2: tiled 2x bilinear upsample (jax half-pixel convention).
// ---------------------------------------------------------------------------
__global__ void k_resize(float* __restrict__ out)
{
    __shared__ float t[18][19];
    const int bc = blockIdx.z;
    const int ih0 = blockIdx.y * 16 - 1;
    const int iw0 = blockIdx.x * 16 - 1;
    const float* yb = g_y + (long)bc * HP * WP;

    const int tx = threadIdx.x, ty = threadIdx.y;
    const int lin = ty * 16 + tx;
    for (int i = lin; i < 18 * 18; i += 256) {
        const int r = i / 18, c = i % 18;
        const int gr = min(max(ih0 + r, 0), HP - 1);
        const int gc = min(max(iw0 + c, 0), WP - 1);
        t[r][c] = yb[gr * WP + gc];
    }
    __syncthreads();

    const int r0 = ty, r1 = ty + 1, r2 = ty + 2;
    const int c0 = tx, c1 = tx + 1, c2 = tx + 2;
    const float a_0 = 0.25f * t[r0][c0] + 0.75f * t[r0][c1];
    const float b_0 = 0.75f * t[r0][c1] + 0.25f * t[r0][c2];
    const float a_1 = 0.25f * t[r1][c0] + 0.75f * t[r1][c1];
    const float b_1 = 0.75f * t[r1][c1] + 0.25f * t[r1][c2];
    const float a_2 = 0.25f * t[r2][c0] + 0.75f * t[r2][c1];
    const float b_2 = 0.75f * t[r2][c1] + 0.25f * t[r2][c2];

    const int oh = 2 * (blockIdx.y * 16 + ty);
    const int ow = 2 * (blockIdx.x * 16 + tx);
    float* obase = out + ((long)bc * 224 + oh) * 224 + ow;
    *reinterpret_cast<float2*>(obase) =
        make_float2(0.25f * a_0 + 0.75f * a_1, 0.25f * b_0 + 0.75f * b_1);
    *reinterpret_cast<float2*>(obase + 224) =
        make_float2(0.75f * a_1 + 0.25f * a_2, 0.75f * b_1 + 0.25f * b_2);
}

extern "C" void kernel_launch(void* const* d_in, const int* in_sizes, int n_in,
                              void* d_out, int out_size)
{
    const float* x   = (const float*)d_in[0];
    const float* wts = (const float*)d_in[1];
    const float* fcw = (const float*)d_in[2];
    const float* fcb = (const float*)d_in[3];
    const float* lng = (const float*)d_in[4];
    const float* lnb = (const float*)d_in[5];
    float* out = (float*)d_out;

    k_precompute<<<1, 512>>>(wts);
    k_pixels<<<(NPIX/2 + 255) / 256, 256>>>(x, fcw, fcb, lng, lnb);
    dim3 rb(16, 16);
    dim3 rg(WP / 16, HP / 16, NB * OC);
    k_resize<<<rg, rb>>>(out);
}

// round 7
// speedup vs baseline: 1.2401x; 1.2401x over previous
#include <cuda_runtime.h>

#define NW 6
#define NL 4
#define HP 112
#define WP 112
#define NB 8
#define OC 16
#define NPIX (NB*HP*WP)

__device__ float g_y[NB*OC*HP*WP];

// ---------------------------------------------------------------------------
// Fused pixels kernel. PROLOGUE (every block, redundant, parallel):
//   circuit sim for the 8 basis states (8 warps, register amplitudes +
//   shuffles) -> M_w = Phi^dag Z_w Phi (product computed ONCE per (i,jj,t),
//   accumulated into 6 signed sums) -> fold (-i)^popcount -> 27-term trig
//   table sT. MAIN: two adjacent patch pixels per thread: 2x2 mean -> trig
//   basis -> 6 exps via sT -> FC -> LayerNorm -> ReLU -> g_y.
// ---------------------------------------------------------------------------
__global__ void __launch_bounds__(256)
k_pixels(const float* __restrict__ x,
         const float* __restrict__ w,
         const float* __restrict__ fcw,
         const float* __restrict__ fcb,
         const float* __restrict__ lng,
         const float* __restrict__ lnb)
{
    __shared__ float2 sU[24][4];
    __shared__ float2 phi[8][64];
    __shared__ float  sD[64][4][13];      // [pair][chunk][q*2+c], padded
    __shared__ float  Mre[6][8][8];
    __shared__ float  Mim[6][8][8];
    __shared__ float  sT[162], sFC[96], sFB[16], sG[16], sB[16];

    const int tid  = threadIdx.x;          // 256 threads = 8 warps
    const int wrp  = tid >> 5;
    const int lane = tid & 31;
    const unsigned FULL = 0xFFFFFFFFu;

    // param staging (independent of circuit)
    if (tid < 96)  sFC[tid] = fcw[tid];
    if (tid >= 96  && tid < 112) sFB[tid - 96]  = fcb[tid - 96];
    if (tid >= 112 && tid < 128) sG [tid - 112] = lng[tid - 112];
    if (tid >= 128 && tid < 144) sB [tid - 128] = lnb[tid - 128];

    if (tid >= 160 && tid < 184) {
        const int gi = tid - 160;
        const float ph = w[gi*3 + 0];
        const float th = w[gi*3 + 1];
        const float om = w[gi*3 + 2];
        const float ch = cosf(0.5f * th), sh = sinf(0.5f * th);
        float cp, sp, cm, sm;
        sincosf(-0.5f * (ph + om), &sp, &cp);   // ep = cp + i sp
        sincosf(-0.5f * (ph - om), &sm, &cm);   // em = cm + i sm
        sU[gi][0] = make_float2( cp*ch,  sp*ch);   // u00
        sU[gi][1] = make_float2(-cm*sh,  sm*sh);   // u01
        sU[gi][2] = make_float2( cm*sh,  sm*sh);   // u10
        sU[gi][3] = make_float2( cp*ch, -sp*ch);   // u11
    }
    __syncthreads();

    // ---- circuit: warp wrp simulates basis state |wrp>|000> ----
    {
        float ar = (lane == wrp * 8) ? 1.f : 0.f, ai = 0.f;
        float br = (lane + 32 == wrp * 8) ? 1.f : 0.f, bi = 0.f;

        for (int l = 0; l < NL; l++) {
            #pragma unroll
            for (int q = 0; q < NW; q++) {
                const float2 u00 = sU[l*6+q][0], u01 = sU[l*6+q][1];
                const float2 u10 = sU[l*6+q][2], u11 = sU[l*6+q][3];
                if (q == 0) {
                    const float nar = u00.x*ar - u00.y*ai + u01.x*br - u01.y*bi;
                    const float nai = u00.x*ai + u00.y*ar + u01.x*bi + u01.y*br;
                    const float nbr = u10.x*ar - u10.y*ai + u11.x*br - u11.y*bi;
                    const float nbi = u10.x*ai + u10.y*ar + u11.x*bi + u11.y*br;
                    ar = nar; ai = nai; br = nbr; bi = nbi;
                } else {
                    const int stride = 1 << (5 - q);
                    const float par = __shfl_xor_sync(FULL, ar, stride);
                    const float pai = __shfl_xor_sync(FULL, ai, stride);
                    const float pbr = __shfl_xor_sync(FULL, br, stride);
                    const float pbi = __shfl_xor_sync(FULL, bi, stride);
                    const bool hi = (lane & stride) != 0;
                    // v' = A*v + B*p  with lo: A=u00,B=u01 ; hi: A=u11,B=u10
                    const float2 A = hi ? u11 : u00;
                    const float2 Bc = hi ? u10 : u01;
                    {
                        const float nr = A.x*ar - A.y*ai + Bc.x*par - Bc.y*pai;
                        const float ni = A.x*ai + A.y*ar + Bc.x*pai + Bc.y*par;
                        ar = nr; ai = ni;
                    }
                    {
                        const float nr = A.x*br - A.y*bi + Bc.x*pbr - Bc.y*pbi;
                        const float ni = A.x*bi + A.y*br + Bc.x*pbi + Bc.y*pbr;
                        br = nr; bi = ni;
                    }
                }
            }
            // CNOT ring composite permutation: new[s] = old[P(s)]
            const int r = l % (NW - 1) + 1;
            int i0 = lane, i1 = lane + 32;
            #pragma unroll
            for (int q = NW - 1; q >= 0; q--) {
                const int cpos = 5 - q;
                const int tpos = 5 - ((q + r) % NW);
                i0 ^= ((i0 >> cpos) & 1) << tpos;
                i1 ^= ((i1 >> cpos) & 1) << tpos;
            }
            const float g0ar = __shfl_sync(FULL, ar, i0 & 31);
            const float g0ai = __shfl_sync(FULL, ai, i0 & 31);
            const float g0br = __shfl_sync(FULL, br, i0 & 31);
            const float g0bi = __shfl_sync(FULL, bi, i0 & 31);
            const float g1ar = __shfl_sync(FULL, ar, i1 & 31);
            const float g1ai = __shfl_sync(FULL, ai, i1 & 31);
            const float g1br = __shfl_sync(FULL, br, i1 & 31);
            const float g1bi = __shfl_sync(FULL, bi, i1 & 31);
            ar = (i0 < 32) ? g0ar : g0br;
            ai = (i0 < 32) ? g0ai : g0bi;
            br = (i1 < 32) ? g1ar : g1br;
            bi = (i1 < 32) ? g1ai : g1bi;
        }
        phi[wrp][lane]      = make_float2(ar, ai);
        phi[wrp][lane + 32] = make_float2(br, bi);
    }
    __syncthreads();

    // ---- Phase D1: thread = (pair, chunk); product once, 6 signed sums ----
    {
        const int pair = tid >> 2, chunk = tid & 3;
        const int i = pair >> 3, jj = pair & 7;
        const float s0 = (chunk & 2) ? -1.f : 1.f;   // q=0 sign (t bit5)
        const float s1 = (chunk & 1) ? -1.f : 1.f;   // q=1 sign (t bit4)
        float acc[12];
        #pragma unroll
        for (int m = 0; m < 12; m++) acc[m] = 0.f;
        #pragma unroll
        for (int k = 0; k < 16; k++) {
            const int t = chunk * 16 + k;
            const float2 a = phi[i][t], b = phi[jj][t];
            const float pre = a.x*b.x + a.y*b.y;
            const float pim = a.x*b.y - a.y*b.x;
            acc[0]  += pre;  acc[1]  += pim;                 // q0 (sign later)
            acc[2]  += pre;  acc[3]  += pim;                 // q1 (sign later)
            if (k & 8) { acc[4] -= pre; acc[5] -= pim; } else { acc[4] += pre; acc[5] += pim; }
            if (k & 4) { acc[6] -= pre; acc[7] -= pim; } else { acc[6] += pre; acc[7] += pim; }
            if (k & 2) { acc[8] -= pre; acc[9] -= pim; } else { acc[8] += pre; acc[9] += pim; }
            if (k & 1) { acc[10] -= pre; acc[11] -= pim; } else { acc[10] += pre; acc[11] += pim; }
        }
        acc[0] *= s0; acc[1] *= s0;
        acc[2] *= s1; acc[3] *= s1;
        #pragma unroll
        for (int m = 0; m < 12; m++) sD[pair][chunk][m] = acc[m];
    }
    __syncthreads();

    // ---- Phase D2: reduce 4 chunks -> Mre/Mim (768 outputs) ----
    for (int o = tid; o < 768; o += 256) {
        const int c = o & 1, pair = (o >> 1) & 63, q = o >> 7;
        float s = sD[pair][0][2*q+c] + sD[pair][1][2*q+c]
                + sD[pair][2][2*q+c] + sD[pair][3][2*q+c];
        const int i = pair >> 3, jj = pair & 7;
        if (c) Mim[q][i][jj] = s; else Mre[q][i][jj] = s;
    }
    __syncthreads();

    // ---- Phase E: 8 contributing (i,jj) pairs per term -> sT ----
    if (tid < 6 * 27) {
        const int q = tid / 27, term = tid % 27;
        const int tt[3] = { term / 9, (term / 3) % 3, term % 3 };
        float acc = 0.f;
        #pragma unroll
        for (int k = 0; k < 8; k++) {
            int i = 0, jj = 0;
            float sgn = 0.125f;
            #pragma unroll
            for (int c = 0; c < 3; c++) {
                const int sel = (k >> c) & 1;
                const int t = tt[c];
                int bi, bj;
                if (t == 2) { bi = sel ^ 1; bj = sel; }
                else {
                    bi = sel; bj = sel;
                    if (t == 1 && sel == 1) sgn = -sgn;
                }
                i  |= bi << (2 - c);
                jj |= bj << (2 - c);
            }
            const int kph = (__popc(i) - __popc(jj)) & 3;
            const float mre = Mre[q][i][jj], mim = Mim[q][i][jj];
            const float f = (kph == 0) ? mre : (kph == 1) ? -mim
                          : (kph == 2) ? -mre : mim;
            acc += sgn * f;
        }
        sT[tid] = acc;
    }
    __syncthreads();

    // ================== MAIN: two patch pixels per thread ==================
    const int pp = blockIdx.x * blockDim.x + tid;
    if (pp >= NPIX / 2) return;
    const int WPH = WP / 2;
    const int b   = pp / (HP * WPH);
    const int rem = pp % (HP * WPH);
    const int hp  = rem / WPH, wpp = rem % WPH;

    float g0[3][3], g1[3][3];
    #pragma unroll
    for (int c = 0; c < 3; c++) {
        const float* base = x + (((long)(b * 3 + c) * 224 + 2 * hp) * 224 + 4 * wpp);
        const float4 r0 = *reinterpret_cast<const float4*>(base);
        const float4 r1 = *reinterpret_cast<const float4*>(base + 224);
        const float a0 = 0.25f * (r0.x + r0.y + r1.x + r1.y);
        const float a1 = 0.25f * (r0.z + r0.w + r1.z + r1.w);
        float sn, cs;
        sincosf(a0, &sn, &cs);
        g0[c][0] = 1.f; g0[c][1] = cs; g0[c][2] = sn;
        sincosf(a1, &sn, &cs);
        g1[c][0] = 1.f; g1[c][1] = cs; g1[c][2] = sn;
    }

    float2 vout[OC];
    #pragma unroll
    for (int half = 0; half < 2; half++) {
        float (*gg)[3] = half ? g1 : g0;

        float e[6];
        #pragma unroll
        for (int q = 0; q < 6; q++) e[q] = 0.f;
        #pragma unroll
        for (int t0 = 0; t0 < 3; t0++)
            #pragma unroll
            for (int t1 = 0; t1 < 3; t1++) {
                const float p01 = gg[0][t0] * gg[1][t1];
                #pragma unroll
                for (int t2 = 0; t2 < 3; t2++) {
                    const float bas = p01 * gg[2][t2];
                    const int t = (t0 * 3 + t1) * 3 + t2;
                    #pragma unroll
                    for (int q = 0; q < 6; q++) e[q] += sT[q * 27 + t] * bas;
                }
            }

        float y[OC], mu = 0.f;
        #pragma unroll
        for (int o = 0; o < OC; o++) {
            float acc = sFB[o];
            #pragma unroll
            for (int q = 0; q < 6; q++) acc += sFC[o * 6 + q] * e[q];
            y[o] = acc;
            mu += acc;
        }
        mu *= (1.f / OC);
        float var = 0.f;
        #pragma unroll
        for (int o = 0; o < OC; o++) { const float d = y[o] - mu; var += d * d; }
        var *= (1.f / OC);
        const float inv = rsqrtf(var + 1e-5f);
        #pragma unroll
        for (int o = 0; o < OC; o++) {
            const float v = fmaxf((y[o] - mu) * inv * sG[o] + sB[o], 0.f);
            if (half) vout[o].y = v; else vout[o].x = v;
        }
    }

    #pragma unroll
    for (int o = 0; o < OC; o++) {
        *reinterpret_cast<float2*>(
            &g_y[(((long)b * OC + o) * HP + hp) * WP + 2 * wpp]) = vout[o];
    }
}

// ---------------------------------------------------------------------------
// Kernel 2: tiled 2x bilinear upsample (jax half-pixel convention).
// ---------------------------------------------------------------------------
__global__ void k_resize(float* __restrict__ out)
{
    __shared__ float t[18][19];
    const int bc = blockIdx.z;
    const int ih0 = blockIdx.y * 16 - 1;
    const int iw0 = blockIdx.x * 16 - 1;
    const float* yb = g_y + (long)bc * HP * WP;

    const int tx = threadIdx.x, ty = threadIdx.y;
    const int lin = ty * 16 + tx;
    for (int i = lin; i < 18 * 18; i += 256) {
        const int r = i / 18, c = i % 18;
        const int gr = min(max(ih0 + r, 0), HP - 1);
        const int gc = min(max(iw0 + c, 0), WP - 1);
        t[r][c] = yb[gr * WP + gc];
    }
    __syncthreads();

    const int r0 = ty, r1 = ty + 1, r2 = ty + 2;
    const int c0 = tx, c1 = tx + 1, c2 = tx + 2;
    const float a_0 = 0.25f * t[r0][c0] + 0.75f * t[r0][c1];
    const float b_0 = 0.75f * t[r0][c1] + 0.25f * t[r0][c2];
    const float a_1 = 0.25f * t[r1][c0] + 0.75f * t[r1][c1];
    const float b_1 = 0.75f * t[r1][c1] + 0.25f * t[r1][c2];
    const float a_2 = 0.25f * t[r2][c0] + 0.75f * t[r2][c1];
    const float b_2 = 0.75f * t[r2][c1] + 0.25f * t[r2][c2];

    const int oh = 2 * (blockIdx.y * 16 + ty);
    const int ow = 2 * (blockIdx.x * 16 + tx);
    float* obase = out + ((long)bc * 224 + oh) * 224 + ow;
    *reinterpret_cast<float2*>(obase) =
        make_float2(0.25f * a_0 + 0.75f * a_1, 0.25f * b_0 + 0.75f * b_1);
    *reinterpret_cast<float2*>(obase + 224) =
        make_float2(0.75f * a_1 + 0.25f * a_2, 0.75f * b_1 + 0.25f * b_2);
}

extern "C" void kernel_launch(void* const* d_in, const int* in_sizes, int n_in,
                              void* d_out, int out_size)
{
    const float* x   = (const float*)d_in[0];
    const float* wts = (const float*)d_in[1];
    const float* fcw = (const float*)d_in[2];
    const float* fcb = (const float*)d_in[3];
    const float* lng = (const float*)d_in[4];
    const float* lnb = (const float*)d_in[5];
    float* out = (float*)d_out;

    k_pixels<<<(NPIX/2 + 255) / 256, 256>>>(x, wts, fcw, fcb, lng, lnb);
    dim3 rb(16, 16);
    dim3 rg(WP / 16, HP / 16, NB * OC);
    k_resize<<<rg, rb>>>(out);
}

// round 9
// speedup vs baseline: 1.4668x; 1.1828x over previous
#include <cuda_runtime.h>

#define NW 6
#define NL 4
#define HP 112
#define WP 112
#define NB 8
#define OC 16
#define NPIX (NB*HP*WP)

__device__ float g_y[NB*OC*HP*WP];

// ---------------------------------------------------------------------------
// Fused pixels kernel. PROLOGUE (per block, redundant, parallel): circuit sim
// for 8 basis states (8 warps, register amplitudes + shuffles) -> M_w =
// Phi^dag Z_w Phi (conflict-free LDS mapping) -> fold phases -> 27-term trig
// table sT. MAIN: two adjacent patch pixels per thread.
// ---------------------------------------------------------------------------
__global__ void __launch_bounds__(256)
k_pixels(const float* __restrict__ x,
         const float* __restrict__ w,
         const float* __restrict__ fcw,
         const float* __restrict__ fcb,
         const float* __restrict__ lng,
         const float* __restrict__ lnb)
{
    __shared__ float2 sU[24][4];
    __shared__ float2 phi[8][65];          // padded row: conflict-free reads
    __shared__ float  sD[4][64][13];       // [chunk][pair][q*2+c], 13-stride
    __shared__ float  Mre[6][8][8];
    __shared__ float  Mim[6][8][8];
    __shared__ float  sT[162], sFC[96], sFB[16], sG[16], sB[16];

    const int tid  = threadIdx.x;          // 256 threads = 8 warps
    const int wrp  = tid >> 5;
    const int lane = tid & 31;
    const unsigned FULL = 0xFFFFFFFFu;

    if (tid < 96)  sFC[tid] = fcw[tid];
    if (tid >= 96  && tid < 112) sFB[tid - 96]  = fcb[tid - 96];
    if (tid >= 112 && tid < 128) sG [tid - 112] = lng[tid - 112];
    if (tid >= 128 && tid < 144) sB [tid - 128] = lnb[tid - 128];

    if (tid >= 160 && tid < 184) {
        const int gi = tid - 160;
        const float ph = w[gi*3 + 0];
        const float th = w[gi*3 + 1];
        const float om = w[gi*3 + 2];
        const float ch = cosf(0.5f * th), sh = sinf(0.5f * th);
        float cp, sp, cm, sm;
        sincosf(-0.5f * (ph + om), &sp, &cp);
        sincosf(-0.5f * (ph - om), &sm, &cm);
        sU[gi][0] = make_float2( cp*ch,  sp*ch);
        sU[gi][1] = make_float2(-cm*sh,  sm*sh);
        sU[gi][2] = make_float2( cm*sh,  sm*sh);
        sU[gi][3] = make_float2( cp*ch, -sp*ch);
    }
    __syncthreads();

    // ---- circuit: warp wrp simulates basis state |wrp>|000> ----
    {
        float ar = (lane == wrp * 8) ? 1.f : 0.f, ai = 0.f;
        float br = (lane + 32 == wrp * 8) ? 1.f : 0.f, bi = 0.f;

        for (int l = 0; l < NL; l++) {
            #pragma unroll
            for (int q = 0; q < NW; q++) {
                const float2 u00 = sU[l*6+q][0], u01 = sU[l*6+q][1];
                const float2 u10 = sU[l*6+q][2], u11 = sU[l*6+q][3];
                if (q == 0) {
                    const float nar = u00.x*ar - u00.y*ai + u01.x*br - u01.y*bi;
                    const float nai = u00.x*ai + u00.y*ar + u01.x*bi + u01.y*br;
                    const float nbr = u10.x*ar - u10.y*ai + u11.x*br - u11.y*bi;
                    const float nbi = u10.x*ai + u10.y*ar + u11.x*bi + u11.y*br;
                    ar = nar; ai = nai; br = nbr; bi = nbi;
                } else {
                    const int stride = 1 << (5 - q);
                    const float par = __shfl_xor_sync(FULL, ar, stride);
                    const float pai = __shfl_xor_sync(FULL, ai, stride);
                    const float pbr = __shfl_xor_sync(FULL, br, stride);
                    const float pbi = __shfl_xor_sync(FULL, bi, stride);
                    const bool hi = (lane & stride) != 0;
                    const float2 A  = hi ? u11 : u00;
                    const float2 Bc = hi ? u10 : u01;
                    {
                        const float nr = A.x*ar - A.y*ai + Bc.x*par - Bc.y*pai;
                        const float ni = A.x*ai + A.y*ar + Bc.x*pai + Bc.y*par;
                        ar = nr; ai = ni;
                    }
                    {
                        const float nr = A.x*br - A.y*bi + Bc.x*pbr - Bc.y*pbi;
                        const float ni = A.x*bi + A.y*br + Bc.x*pbi + Bc.y*pbr;
                        br = nr; bi = ni;
                    }
                }
            }
            const int r = l % (NW - 1) + 1;
            int i0 = lane, i1 = lane + 32;
            #pragma unroll
            for (int q = NW - 1; q >= 0; q--) {
                const int cpos = 5 - q;
                const int tpos = 5 - ((q + r) % NW);
                i0 ^= ((i0 >> cpos) & 1) << tpos;
                i1 ^= ((i1 >> cpos) & 1) << tpos;
            }
            const float g0ar = __shfl_sync(FULL, ar, i0 & 31);
            const float g0ai = __shfl_sync(FULL, ai, i0 & 31);
            const float g0br = __shfl_sync(FULL, br, i0 & 31);
            const float g0bi = __shfl_sync(FULL, bi, i0 & 31);
            const float g1ar = __shfl_sync(FULL, ar, i1 & 31);
            const float g1ai = __shfl_sync(FULL, ai, i1 & 31);
            const float g1br = __shfl_sync(FULL, br, i1 & 31);
            const float g1bi = __shfl_sync(FULL, bi, i1 & 31);
            ar = (i0 < 32) ? g0ar : g0br;
            ai = (i0 < 32) ? g0ai : g0bi;
            br = (i1 < 32) ? g1ar : g1br;
            bi = (i1 < 32) ? g1ai : g1bi;
        }
        phi[wrp][lane]      = make_float2(ar, ai);
        phi[wrp][lane + 32] = make_float2(br, bi);
    }
    __syncthreads();

    // ---- Phase D1: pair = tid&63 (fast), chunk = tid>>6 (slow) ----
    {
        const int pair = tid & 63, chunk = tid >> 6;
        const int i = pair >> 3, jj = pair & 7;
        const float s0 = (chunk & 2) ? -1.f : 1.f;   // t bit5 sign (q=0)
        const float s1 = (chunk & 1) ? -1.f : 1.f;   // t bit4 sign (q=1)
        float acc[12];
        #pragma unroll
        for (int m = 0; m < 12; m++) acc[m] = 0.f;
        #pragma unroll
        for (int k = 0; k < 16; k++) {
            const int t = chunk * 16 + k;
            const float2 a = phi[i][t], b = phi[jj][t];
            const float pre = a.x*b.x + a.y*b.y;
            const float pim = a.x*b.y - a.y*b.x;
            acc[0]  += pre;  acc[1]  += pim;
            acc[2]  += pre;  acc[3]  += pim;
            if (k & 8) { acc[4] -= pre; acc[5] -= pim; } else { acc[4] += pre; acc[5] += pim; }
            if (k & 4) { acc[6] -= pre; acc[7] -= pim; } else { acc[6] += pre; acc[7] += pim; }
            if (k & 2) { acc[8] -= pre; acc[9] -= pim; } else { acc[8] += pre; acc[9] += pim; }
            if (k & 1) { acc[10] -= pre; acc[11] -= pim; } else { acc[10] += pre; acc[11] += pim; }
        }
        acc[0] *= s0; acc[1] *= s0;
        acc[2] *= s1; acc[3] *= s1;
        #pragma unroll
        for (int m = 0; m < 12; m++) sD[chunk][pair][m] = acc[m];
    }
    __syncthreads();

    // ---- Phase D2: reduce 4 chunks -> Mre/Mim ----
    for (int o = tid; o < 768; o += 256) {
        const int c = o & 1, pair = (o >> 1) & 63, q = o >> 7;
        const float s = sD[0][pair][2*q+c] + sD[1][pair][2*q+c]
                      + sD[2][pair][2*q+c] + sD[3][pair][2*q+c];
        const int i = pair >> 3, jj = pair & 7;
        if (c) Mim[q][i][jj] = s; else Mre[q][i][jj] = s;
    }
    __syncthreads();

    // ---- Phase E: 8 contributing (i,jj) pairs per term -> sT ----
    if (tid < 6 * 27) {
        const int q = tid / 27, term = tid % 27;
        const int tt[3] = { term / 9, (term / 3) % 3, term % 3 };
        float acc = 0.f;
        #pragma unroll
        for (int k = 0; k < 8; k++) {
            int i = 0, jj = 0;
            float sgn = 0.125f;
            #pragma unroll
            for (int c = 0; c < 3; c++) {
                const int sel = (k >> c) & 1;
                const int t = tt[c];
                int bi, bj;
                if (t == 2) { bi = sel ^ 1; bj = sel; }
                else {
                    bi = sel; bj = sel;
                    if (t == 1 && sel == 1) sgn = -sgn;
                }
                i  |= bi << (2 - c);
                jj |= bj << (2 - c);
            }
            const int kph = (__popc(i) - __popc(jj)) & 3;
            const float mre = Mre[q][i][jj], mim = Mim[q][i][jj];
            const float f = (kph == 0) ? mre : (kph == 1) ? -mim
                          : (kph == 2) ? -mre : mim;
            acc += sgn * f;
        }
        sT[tid] = acc;
    }
    __syncthreads();

    // ================== MAIN: two patch pixels per thread ==================
    const int pp = blockIdx.x * blockDim.x + tid;   // grid sized exactly
    const int WPH = WP / 2;
    const int b   = pp / (HP * WPH);
    const int rem = pp % (HP * WPH);
    const int hp  = rem / WPH, wpp = rem % WPH;

    float g0[3][3], g1[3][3];
    #pragma unroll
    for (int c = 0; c < 3; c++) {
        const float* base = x + (((long)(b * 3 + c) * 224 + 2 * hp) * 224 + 4 * wpp);
        const float4 r0 = *reinterpret_cast<const float4*>(base);
        const float4 r1 = *reinterpret_cast<const float4*>(base + 224);
        const float a0 = 0.25f * (r0.x + r0.y + r1.x + r1.y);
        const float a1 = 0.25f * (r0.z + r0.w + r1.z + r1.w);
        float sn, cs;
        sincosf(a0, &sn, &cs);
        g0[c][0] = 1.f; g0[c][1] = cs; g0[c][2] = sn;
        sincosf(a1, &sn, &cs);
        g1[c][0] = 1.f; g1[c][1] = cs; g1[c][2] = sn;
    }

    float2 vout[OC];
    #pragma unroll
    for (int half = 0; half < 2; half++) {
        float (*gg)[3] = half ? g1 : g0;

        float e[6];
        #pragma unroll
        for (int q = 0; q < 6; q++) e[q] = 0.f;
        #pragma unroll
        for (int t0 = 0; t0 < 3; t0++)
            #pragma unroll
            for (int t1 = 0; t1 < 3; t1++) {
                const float p01 = gg[0][t0] * gg[1][t1];
                #pragma unroll
                for (int t2 = 0; t2 < 3; t2++) {
                    const float bas = p01 * gg[2][t2];
                    const int t = (t0 * 3 + t1) * 3 + t2;
                    #pragma unroll
                    for (int q = 0; q < 6; q++) e[q] += sT[q * 27 + t] * bas;
                }
            }

        float y[OC], mu = 0.f;
        #pragma unroll
        for (int o = 0; o < OC; o++) {
            float acc = sFB[o];
            #pragma unroll
            for (int q = 0; q < 6; q++) acc += sFC[o * 6 + q] * e[q];
            y[o] = acc;
            mu += acc;
        }
        mu *= (1.f / OC);
        float var = 0.f;
        #pragma unroll
        for (int o = 0; o < OC; o++) { const float d = y[o] - mu; var += d * d; }
        var *= (1.f / OC);
        const float inv = rsqrtf(var + 1e-5f);
        #pragma unroll
        for (int o = 0; o < OC; o++) {
            const float v = fmaxf((y[o] - mu) * inv * sG[o] + sB[o], 0.f);
            if (half) vout[o].y = v; else vout[o].x = v;
        }
    }

    #pragma unroll
    for (int o = 0; o < OC; o++) {
        *reinterpret_cast<float2*>(
            &g_y[(((long)b * OC + o) * HP + hp) * WP + 2 * wpp]) = vout[o];
    }
}

// ---------------------------------------------------------------------------
// Kernel 2 (v2 + barrier fix): 2x bilinear upsample, full-row tiles.
// Block covers 8 input rows x 112 cols (output 16 x 224). Shared 10x116
// loaded as aligned float2, clamp on row only; __syncthreads BEFORE the
// column-halo copies (they read cells written by other threads).
// Work item = 2 output rows x 4 output cols, two STG.128.
// ---------------------------------------------------------------------------
__global__ void __launch_bounds__(256)
k_resize(float* __restrict__ out)
{
    __shared__ float t[10][116];
    const int by = blockIdx.x;            // 14 row tiles
    const int bc = blockIdx.y;            // 128 (b, oc) planes
    const float* yb = g_y + (long)bc * HP * WP;
    const int tid = threadIdx.x;

    // load rows 8*by-1 .. 8*by+8 (clamped), cols 0..111 at t[r][c+1]
    #pragma unroll
    for (int i = tid; i < 640; i += 256) {
        const int r = i >> 6, c2 = i & 63;
        if (c2 < 56) {
            const int gr = min(max(8 * by - 1 + r, 0), HP - 1);
            const float2 v = *reinterpret_cast<const float2*>(&yb[gr * WP + 2 * c2]);
            t[r][2 * c2 + 1] = v.x;
            t[r][2 * c2 + 2] = v.y;
        }
    }
    __syncthreads();   // tile fully written before halo copies read it

    // column halos: t[r][0] = col0 (clamp), t[r][113] = col111 (clamp)
    if (tid < 10)              t[tid][0]        = t[tid][1];
    else if (tid < 20)         t[tid - 10][113] = t[tid - 10][112];
    __syncthreads();

    // work items: rp = j>>6 (0..7), c4 = j&63 (<56): out rows 2*(8by+rp)+{0,1},
    // out cols 4*c4 .. 4*c4+3
    #pragma unroll
    for (int j = tid; j < 512; j += 256) {
        const int rp = j >> 6, c4 = j & 63;
        if (c4 >= 56) continue;
        const int cc = 2 * c4;            // shared col of input m (offset +1)
        float hA[3], hB[3], hC[3], hD[3];
        #pragma unroll
        for (int rr = 0; rr < 3; rr++) {
            const float vm1 = t[rp + rr][cc];
            const float v0  = t[rp + rr][cc + 1];
            const float v1  = t[rp + rr][cc + 2];
            const float v2  = t[rp + rr][cc + 3];
            hA[rr] = 0.25f * vm1 + 0.75f * v0;
            hB[rr] = 0.75f * v0  + 0.25f * v1;
            hC[rr] = 0.25f * v0  + 0.75f * v1;
            hD[rr] = 0.75f * v1  + 0.25f * v2;
        }
        const int oh = 16 * by + 2 * rp;
        float* obase = out + (((long)bc * 224 + oh) * 224 + 4 * c4);
        *reinterpret_cast<float4*>(obase) = make_float4(
            0.25f * hA[0] + 0.75f * hA[1],
            0.25f * hB[0] + 0.75f * hB[1],
            0.25f * hC[0] + 0.75f * hC[1],
            0.25f * hD[0] + 0.75f * hD[1]);
        *reinterpret_cast<float4*>(obase + 224) = make_float4(
            0.75f * hA[1] + 0.25f * hA[2],
            0.75f * hB[1] + 0.25f * hB[2],
            0.75f * hC[1] + 0.25f * hC[2],
            0.75f * hD[1] + 0.25f * hD[2]);
    }
}

extern "C" void kernel_launch(void* const* d_in, const int* in_sizes, int n_in,
                              void* d_out, int out_size)
{
    const float* x   = (const float*)d_in[0];
    const float* wts = (const float*)d_in[1];
    const float* fcw = (const float*)d_in[2];
    const float* fcb = (const float*)d_in[3];
    const float* lng = (const float*)d_in[4];
    const float* lnb = (const float*)d_in[5];
    float* out = (float*)d_out;

    k_pixels<<<NPIX / 2 / 256, 256>>>(x, wts, fcw, fcb, lng, lnb);
    dim3 rg(HP / 8, NB * OC);
    k_resize<<<rg, 256>>>(out);
}

// round 10
// speedup vs baseline: 1.6430x; 1.1201x over previous
#include <cuda_runtime.h>

#define NW 6
#define NL 4
#define HP 112
#define WP 112
#define NB 8
#define OC 16
#define NPIX (NB*HP*WP)

__device__ float g_y[NB*OC*HP*WP];

// ---------------------------------------------------------------------------
// Fused pixels kernel. PROLOGUE (per block, redundant, parallel): circuit sim
// for 8 basis states (8 warps, register amplitudes + shuffles) -> M_w =
// Phi^dag Z_w Phi (conflict-free LDS mapping) -> fold phases -> 27-term trig
// table sT. MAIN: two adjacent patch pixels per thread (fast sincos).
// ---------------------------------------------------------------------------
__global__ void __launch_bounds__(256)
k_pixels(const float* __restrict__ x,
         const float* __restrict__ w,
         const float* __restrict__ fcw,
         const float* __restrict__ fcb,
         const float* __restrict__ lng,
         const float* __restrict__ lnb)
{
    __shared__ float2 sU[24][4];
    __shared__ float2 phi[8][65];          // padded row: conflict-free reads
    __shared__ float  sD[4][64][13];       // [chunk][pair][q*2+c], 13-stride
    __shared__ float  Mre[6][8][8];
    __shared__ float  Mim[6][8][8];
    __shared__ float  sT[162], sFC[96], sFB[16], sG[16], sB[16];

    const int tid  = threadIdx.x;          // 256 threads = 8 warps
    const int wrp  = tid >> 5;
    const int lane = tid & 31;
    const unsigned FULL = 0xFFFFFFFFu;

    if (tid < 96)  sFC[tid] = fcw[tid];
    if (tid >= 96  && tid < 112) sFB[tid - 96]  = fcb[tid - 96];
    if (tid >= 112 && tid < 128) sG [tid - 112] = lng[tid - 112];
    if (tid >= 128 && tid < 144) sB [tid - 128] = lnb[tid - 128];

    if (tid >= 160 && tid < 184) {
        const int gi = tid - 160;
        const float ph = w[gi*3 + 0];
        const float th = w[gi*3 + 1];
        const float om = w[gi*3 + 2];
        const float ch = cosf(0.5f * th), sh = sinf(0.5f * th);
        float cp, sp, cm, sm;
        sincosf(-0.5f * (ph + om), &sp, &cp);
        sincosf(-0.5f * (ph - om), &sm, &cm);
        sU[gi][0] = make_float2( cp*ch,  sp*ch);
        sU[gi][1] = make_float2(-cm*sh,  sm*sh);
        sU[gi][2] = make_float2( cm*sh,  sm*sh);
        sU[gi][3] = make_float2( cp*ch, -sp*ch);
    }
    __syncthreads();

    // ---- circuit: warp wrp simulates basis state |wrp>|000> ----
    {
        float ar = (lane == wrp * 8) ? 1.f : 0.f, ai = 0.f;
        float br = (lane + 32 == wrp * 8) ? 1.f : 0.f, bi = 0.f;

        for (int l = 0; l < NL; l++) {
            #pragma unroll
            for (int q = 0; q < NW; q++) {
                const float2 u00 = sU[l*6+q][0], u01 = sU[l*6+q][1];
                const float2 u10 = sU[l*6+q][2], u11 = sU[l*6+q][3];
                if (q == 0) {
                    const float nar = u00.x*ar - u00.y*ai + u01.x*br - u01.y*bi;
                    const float nai = u00.x*ai + u00.y*ar + u01.x*bi + u01.y*br;
                    const float nbr = u10.x*ar - u10.y*ai + u11.x*br - u11.y*bi;
                    const float nbi = u10.x*ai + u10.y*ar + u11.x*bi + u11.y*br;
                    ar = nar; ai = nai; br = nbr; bi = nbi;
                } else {
                    const int stride = 1 << (5 - q);
                    const float par = __shfl_xor_sync(FULL, ar, stride);
                    const float pai = __shfl_xor_sync(FULL, ai, stride);
                    const float pbr = __shfl_xor_sync(FULL, br, stride);
                    const float pbi = __shfl_xor_sync(FULL, bi, stride);
                    const bool hi = (lane & stride) != 0;
                    const float2 A  = hi ? u11 : u00;
                    const float2 Bc = hi ? u10 : u01;
                    {
                        const float nr = A.x*ar - A.y*ai + Bc.x*par - Bc.y*pai;
                        const float ni = A.x*ai + A.y*ar + Bc.x*pai + Bc.y*par;
                        ar = nr; ai = ni;
                    }
                    {
                        const float nr = A.x*br - A.y*bi + Bc.x*pbr - Bc.y*pbi;
                        const float ni = A.x*bi + A.y*br + Bc.x*pbi + Bc.y*pbr;
                        br = nr; bi = ni;
                    }
                }
            }
            const int r = l % (NW - 1) + 1;
            int i0 = lane, i1 = lane + 32;
            #pragma unroll
            for (int q = NW - 1; q >= 0; q--) {
                const int cpos = 5 - q;
                const int tpos = 5 - ((q + r) % NW);
                i0 ^= ((i0 >> cpos) & 1) << tpos;
                i1 ^= ((i1 >> cpos) & 1) << tpos;
            }
            const float g0ar = __shfl_sync(FULL, ar, i0 & 31);
            const float g0ai = __shfl_sync(FULL, ai, i0 & 31);
            const float g0br = __shfl_sync(FULL, br, i0 & 31);
            const float g0bi = __shfl_sync(FULL, bi, i0 & 31);
            const float g1ar = __shfl_sync(FULL, ar, i1 & 31);
            const float g1ai = __shfl_sync(FULL, ai, i1 & 31);
            const float g1br = __shfl_sync(FULL, br, i1 & 31);
            const float g1bi = __shfl_sync(FULL, bi, i1 & 31);
            ar = (i0 < 32) ? g0ar : g0br;
            ai = (i0 < 32) ? g0ai : g0bi;
            br = (i1 < 32) ? g1ar : g1br;
            bi = (i1 < 32) ? g1ai : g1bi;
        }
        phi[wrp][lane]      = make_float2(ar, ai);
        phi[wrp][lane + 32] = make_float2(br, bi);
    }
    __syncthreads();

    // ---- Phase D1: pair = tid&63 (fast), chunk = tid>>6 (slow) ----
    {
        const int pair = tid & 63, chunk = tid >> 6;
        const int i = pair >> 3, jj = pair & 7;
        const float s0 = (chunk & 2) ? -1.f : 1.f;
        const float s1 = (chunk & 1) ? -1.f : 1.f;
        float acc[12];
        #pragma unroll
        for (int m = 0; m < 12; m++) acc[m] = 0.f;
        #pragma unroll
        for (int k = 0; k < 16; k++) {
            const int t = chunk * 16 + k;
            const float2 a = phi[i][t], b = phi[jj][t];
            const float pre = a.x*b.x + a.y*b.y;
            const float pim = a.x*b.y - a.y*b.x;
            acc[0]  += pre;  acc[1]  += pim;
            acc[2]  += pre;  acc[3]  += pim;
            if (k & 8) { acc[4] -= pre; acc[5] -= pim; } else { acc[4] += pre; acc[5] += pim; }
            if (k & 4) { acc[6] -= pre; acc[7] -= pim; } else { acc[6] += pre; acc[7] += pim; }
            if (k & 2) { acc[8] -= pre; acc[9] -= pim; } else { acc[8] += pre; acc[9] += pim; }
            if (k & 1) { acc[10] -= pre; acc[11] -= pim; } else { acc[10] += pre; acc[11] += pim; }
        }
        acc[0] *= s0; acc[1] *= s0;
        acc[2] *= s1; acc[3] *= s1;
        #pragma unroll
        for (int m = 0; m < 12; m++) sD[chunk][pair][m] = acc[m];
    }
    __syncthreads();

    // ---- Phase D2: reduce 4 chunks -> Mre/Mim ----
    for (int o = tid; o < 768; o += 256) {
        const int c = o & 1, pair = (o >> 1) & 63, q = o >> 7;
        const float s = sD[0][pair][2*q+c] + sD[1][pair][2*q+c]
                      + sD[2][pair][2*q+c] + sD[3][pair][2*q+c];
        const int i = pair >> 3, jj = pair & 7;
        if (c) Mim[q][i][jj] = s; else Mre[q][i][jj] = s;
    }
    __syncthreads();

    // ---- Phase E: 8 contributing (i,jj) pairs per term -> sT ----
    if (tid < 6 * 27) {
        const int q = tid / 27, term = tid % 27;
        const int tt[3] = { term / 9, (term / 3) % 3, term % 3 };
        float acc = 0.f;
        #pragma unroll
        for (int k = 0; k < 8; k++) {
            int i = 0, jj = 0;
            float sgn = 0.125f;
            #pragma unroll
            for (int c = 0; c < 3; c++) {
                const int sel = (k >> c) & 1;
                const int t = tt[c];
                int bi, bj;
                if (t == 2) { bi = sel ^ 1; bj = sel; }
                else {
                    bi = sel; bj = sel;
                    if (t == 1 && sel == 1) sgn = -sgn;
                }
                i  |= bi << (2 - c);
                jj |= bj << (2 - c);
            }
            const int kph = (__popc(i) - __popc(jj)) & 3;
            const float mre = Mre[q][i][jj], mim = Mim[q][i][jj];
            const float f = (kph == 0) ? mre : (kph == 1) ? -mim
                          : (kph == 2) ? -mre : mim;
            acc += sgn * f;
        }
        sT[tid] = acc;
    }
    __syncthreads();

    // ================== MAIN: two patch pixels per thread ==================
    const int pp = blockIdx.x * blockDim.x + tid;
    const int WPH = WP / 2;
    const int b   = pp / (HP * WPH);
    const int rem = pp % (HP * WPH);
    const int hp  = rem / WPH, wpp = rem % WPH;

    float g0[3][3], g1[3][3];
    #pragma unroll
    for (int c = 0; c < 3; c++) {
        const float* base = x + (((long)(b * 3 + c) * 224 + 2 * hp) * 224 + 4 * wpp);
        const float4 r0 = *reinterpret_cast<const float4*>(base);
        const float4 r1 = *reinterpret_cast<const float4*>(base + 224);
        const float a0 = 0.25f * (r0.x + r0.y + r1.x + r1.y);
        const float a1 = 0.25f * (r0.z + r0.w + r1.z + r1.w);
        float sn, cs;
        __sincosf(a0, &sn, &cs);               // |a| small: approx is safe
        g0[c][0] = 1.f; g0[c][1] = cs; g0[c][2] = sn;
        __sincosf(a1, &sn, &cs);
        g1[c][0] = 1.f; g1[c][1] = cs; g1[c][2] = sn;
    }

    float2 vout[OC];
    #pragma unroll
    for (int half = 0; half < 2; half++) {
        float (*gg)[3] = half ? g1 : g0;

        float e[6];
        #pragma unroll
        for (int q = 0; q < 6; q++) e[q] = 0.f;
        #pragma unroll
        for (int t0 = 0; t0 < 3; t0++)
            #pragma unroll
            for (int t1 = 0; t1 < 3; t1++) {
                const float p01 = gg[0][t0] * gg[1][t1];
                #pragma unroll
                for (int t2 = 0; t2 < 3; t2++) {
                    const float bas = p01 * gg[2][t2];
                    const int t = (t0 * 3 + t1) * 3 + t2;
                    #pragma unroll
                    for (int q = 0; q < 6; q++) e[q] += sT[q * 27 + t] * bas;
                }
            }

        float y[OC], mu = 0.f;
        #pragma unroll
        for (int o = 0; o < OC; o++) {
            float acc = sFB[o];
            #pragma unroll
            for (int q = 0; q < 6; q++) acc += sFC[o * 6 + q] * e[q];
            y[o] = acc;
            mu += acc;
        }
        mu *= (1.f / OC);
        float var = 0.f;
        #pragma unroll
        for (int o = 0; o < OC; o++) { const float d = y[o] - mu; var += d * d; }
        var *= (1.f / OC);
        const float inv = rsqrtf(var + 1e-5f);
        #pragma unroll
        for (int o = 0; o < OC; o++) {
            const float v = fmaxf((y[o] - mu) * inv * sG[o] + sB[o], 0.f);
            if (half) vout[o].y = v; else vout[o].x = v;
        }
    }

    #pragma unroll
    for (int o = 0; o < OC; o++) {
        *reinterpret_cast<float2*>(
            &g_y[(((long)b * OC + o) * HP + hp) * WP + 2 * wpp]) = vout[o];
    }
}

// ---------------------------------------------------------------------------
// Kernel 2 (v3): 2x bilinear upsample, pure register gather (no smem).
// One thread = 2 output rows x 4 output cols. g_y (6.4MB) is L1/L2-hot;
// each thread: 9 LDG (middle pair as aligned float2), ~56 FMA, 2 STG.128.
// jax half-pixel weights: even out = 0.25*y[m-1]+0.75*y[m] (clamped),
// odd out = 0.75*y[m]+0.25*y[m+1] (clamped).
// ---------------------------------------------------------------------------
__global__ void __launch_bounds__(256)
k_resize(float* __restrict__ out)
{
    const int idx = blockIdx.x * 256 + threadIdx.x;   // 3136 blocks exactly
    const int c4 = idx % 56;                          // 4-col output group
    const int m  = (idx / 56) % HP;                   // input row
    const int pl = idx / (56 * HP);                   // (b, oc) plane
    const float* yb = g_y + (long)pl * HP * WP;

    const int rm = max(m - 1, 0), rp = min(m + 1, HP - 1);
    const int c0 = 2 * c4;
    const int cm = max(c0 - 1, 0), c2 = min(c0 + 2, WP - 1);

    float hA[3], hB[3], hC[3], hD[3];
    const int rows[3] = { rm, m, rp };
    #pragma unroll
    for (int r = 0; r < 3; r++) {
        const float* rowp = yb + rows[r] * WP;
        const float  vm1 = __ldg(rowp + cm);
        const float2 v01 = *reinterpret_cast<const float2*>(rowp + c0);
        const float  v2  = __ldg(rowp + c2);
        hA[r] = 0.25f * vm1   + 0.75f * v01.x;
        hB[r] = 0.75f * v01.x + 0.25f * v01.y;
        hC[r] = 0.25f * v01.x + 0.75f * v01.y;
        hD[r] = 0.75f * v01.y + 0.25f * v2;
    }

    float* obase = out + (((long)pl * 224 + 2 * m) * 224 + 4 * c4);
    *reinterpret_cast<float4*>(obase) = make_float4(
        0.25f * hA[0] + 0.75f * hA[1],
        0.25f * hB[0] + 0.75f * hB[1],
        0.25f * hC[0] + 0.75f * hC[1],
        0.25f * hD[0] + 0.75f * hD[1]);
    *reinterpret_cast<float4*>(obase + 224) = make_float4(
        0.75f * hA[1] + 0.25f * hA[2],
        0.75f * hB[1] + 0.25f * hB[2],
        0.75f * hC[1] + 0.25f * hC[2],
        0.75f * hD[1] + 0.25f * hD[2]);
}

extern "C" void kernel_launch(void* const* d_in, const int* in_sizes, int n_in,
                              void* d_out, int out_size)
{
    const float* x   = (const float*)d_in[0];
    const float* wts = (const float*)d_in[1];
    const float* fcw = (const float*)d_in[2];
    const float* fcb = (const float*)d_in[3];
    const float* lng = (const float*)d_in[4];
    const float* lnb = (const float*)d_in[5];
    float* out = (float*)d_out;

    k_pixels<<<NPIX / 2 / 256, 256>>>(x, wts, fcw, fcb, lng, lnb);
    k_resize<<<(56 * HP * NB * OC) / 256, 256>>>(out);
}